// round 3
// baseline (speedup 1.0000x reference)
#include <cuda_runtime.h>
#include <cuda_bf16.h>
#include <math.h>
#include <stdint.h>

// Problem constants
#define C_DIM 2048
#define N_EXP 64
#define MAX_N 16384
#define HB 128           // tokens per histogram/rank block
#define MAX_NB (MAX_N / HB)

#define TM 64
#define BK 64

// ---------------- scratch (device globals; no allocation allowed) -------------
__device__ int   g_top1[MAX_N];
__device__ int   g_top2[MAX_N];
__device__ float g_p1[MAX_N];
__device__ float g_p2[MAX_N];
__device__ int   g_hist0[MAX_NB * N_EXP];
__device__ int   g_hist1[MAX_NB * N_EXP];
__device__ int   g_off0[MAX_NB * N_EXP];
__device__ int   g_off1[MAX_NB * N_EXP];

__device__ __forceinline__ uint32_t cvta_smem(const void* p) {
    uint32_t a;
    asm("{ .reg .u64 t; cvta.to.shared.u64 t, %1; cvt.u32.u64 %0, t; }"
        : "=r"(a) : "l"(p));
    return a;
}

// ---------------- K1: gating GEMM + fused top-2/softmax ----------------------
// Block: 64 tokens x 64 experts, BK=64, 256 threads, thread tile 4 tokens x 4 experts.
// Data packed for fma.rn.f32x2:
//   xs2[t][k]  = (x[t][k], x[t][k])           (lane-duplicated)
//   ws2[p][k]  = (w[2p][k], w[2p+1][k])       (expert-pair interleaved)
union GemmSmem {
    struct {
        float2 xs2[TM][BK];        // 32 KB
        float2 ws2[N_EXP / 2][BK]; // 16 KB
    } g;
    float lg[TM][N_EXP + 1];       // logits staging for fused top-2 (16.6 KB)
};

__global__ __launch_bounds__(256) void k_gemm(const float* __restrict__ x,
                                              const float* __restrict__ w) {
    __shared__ GemmSmem sm;

    const int tid = threadIdx.x;
    const int block_t0 = blockIdx.x * TM;
    const int tg = tid >> 4;          // 0..15
    const int eg = tid & 15;          // 0..15
    const int t0 = tg << 2;           // token offset within tile
    const int p0 = eg << 1;           // expert-pair offset (covers experts eg*4..eg*4+3)

    unsigned long long acc[4][2];     // [token][expert-pair] packed f32x2
#pragma unroll
    for (int i = 0; i < 4; i++) { acc[i][0] = 0ull; acc[i][1] = 0ull; }

    const uint32_t xbase = cvta_smem(&sm.g.xs2[t0][0]);
    const uint32_t wbase = cvta_smem(&sm.g.ws2[p0][0]);

    for (int k0 = 0; k0 < C_DIM; k0 += BK) {
        // ---- cooperative packed tile load ----
        // x: 64 rows x 16 float4 groups = 1024, 4 per thread
#pragma unroll
        for (int l = 0; l < 4; l++) {
            int idx = tid + l * 256;
            int r   = idx >> 4;
            int c4  = idx & 15;
            float4 v = *(const float4*)&x[(size_t)(block_t0 + r) * C_DIM + k0 + (c4 << 2)];
            float4* dst = (float4*)&sm.g.xs2[r][c4 << 2];
            dst[0] = make_float4(v.x, v.x, v.y, v.y);
            dst[1] = make_float4(v.z, v.z, v.w, v.w);
        }
        // w: 32 pairs x 16 float4 groups = 512, 2 per thread
#pragma unroll
        for (int l = 0; l < 2; l++) {
            int idx = tid + l * 256;
            int p   = idx >> 4;
            int c4  = idx & 15;
            float4 a = *(const float4*)&w[(size_t)(2 * p)     * C_DIM + k0 + (c4 << 2)];
            float4 b = *(const float4*)&w[(size_t)(2 * p + 1) * C_DIM + k0 + (c4 << 2)];
            float4* dst = (float4*)&sm.g.ws2[p][c4 << 2];
            dst[0] = make_float4(a.x, b.x, a.y, b.y);
            dst[1] = make_float4(a.z, b.z, a.w, b.w);
        }
        __syncthreads();

        // ---- packed FFMA2 inner loop: 2 k-steps per iteration ----
#pragma unroll 4
        for (int kk = 0; kk < BK; kk += 2) {
            unsigned long long xa0[4], xa1[4];
#pragma unroll
            for (int i = 0; i < 4; i++) {
                uint32_t addr = xbase + i * (BK * 8) + kk * 8;
                asm("ld.shared.v2.b64 {%0, %1}, [%2];"
                    : "=l"(xa0[i]), "=l"(xa1[i]) : "r"(addr));
            }
            unsigned long long wb0[2], wb1[2];
#pragma unroll
            for (int j = 0; j < 2; j++) {
                uint32_t addr = wbase + j * (BK * 8) + kk * 8;
                asm("ld.shared.v2.b64 {%0, %1}, [%2];"
                    : "=l"(wb0[j]), "=l"(wb1[j]) : "r"(addr));
            }
#pragma unroll
            for (int i = 0; i < 4; i++) {
#pragma unroll
                for (int j = 0; j < 2; j++) {
                    asm("fma.rn.f32x2 %0, %1, %2, %0;"
                        : "+l"(acc[i][j]) : "l"(xa0[i]), "l"(wb0[j]));
                    asm("fma.rn.f32x2 %0, %1, %2, %0;"
                        : "+l"(acc[i][j]) : "l"(xa1[i]), "l"(wb1[j]));
                }
            }
        }
        __syncthreads();
    }

    // ---- epilogue: stage logits in smem, fused top-2 + softmax ----
#pragma unroll
    for (int i = 0; i < 4; i++) {
#pragma unroll
        for (int j = 0; j < 2; j++) {
            unsigned long long v = acc[i][j];
            float lo = __uint_as_float((unsigned int)(v & 0xffffffffull));
            float hi = __uint_as_float((unsigned int)(v >> 32));
            int e = (p0 + j) * 2;
            sm.lg[t0 + i][e]     = lo;
            sm.lg[t0 + i][e + 1] = hi;
        }
    }
    __syncthreads();

    if (tid < TM) {
        const float* row = &sm.lg[tid][0];
        float b1 = -INFINITY, b2 = -INFINITY;
        int i1 = 0, i2 = 0;
#pragma unroll 8
        for (int e = 0; e < N_EXP; e++) {
            float v = row[e];
            if (v > b1) { b2 = b1; i2 = i1; b1 = v; i1 = e; }
            else if (v > b2) { b2 = v; i2 = e; }
        }
        float e2 = expf(b2 - b1);
        float inv = 1.0f / (1.0f + e2);
        int n = block_t0 + tid;
        g_top1[n] = i1; g_top2[n] = i2;
        g_p1[n] = inv;
        g_p2[n] = e2 * inv;
    }
}

// ---------------- K2: per-block expert histograms ----------------------------
__global__ void k_hist() {
    __shared__ int h0[N_EXP], h1[N_EXP];
    int tid = threadIdx.x;
    int b = blockIdx.x;
    if (tid < N_EXP) { h0[tid] = 0; h1[tid] = 0; }
    __syncthreads();
    int n = b * HB + tid;
    atomicAdd(&h0[g_top1[n]], 1);
    atomicAdd(&h1[g_top2[n]], 1);
    __syncthreads();
    if (tid < N_EXP) {
        g_hist0[b * N_EXP + tid] = h0[tid];
        g_hist1[b * N_EXP + tid] = h1[tid];
    }
}

// ---------------- K3: parallel per-expert prefix over blocks -----------------
// grid = 64 blocks (one expert each), 32 threads. Lane L owns hist blocks
// 4L..4L+3. Register mini-scan + warp shfl scan. off1 = total0 + prefix(hist1).
__global__ void k_prefix(int NB) {
    const int e = blockIdx.x;
    const int lane = threadIdx.x;
    const int base = lane * 4;

    int v[4];
#pragma unroll
    for (int q = 0; q < 4; q++)
        v[q] = (base + q < NB) ? g_hist0[(base + q) * N_EXP + e] : 0;
    int s = v[0] + v[1] + v[2] + v[3];
    int incl = s;
#pragma unroll
    for (int d = 1; d < 32; d <<= 1) {
        int t = __shfl_up_sync(0xffffffffu, incl, d);
        if (lane >= d) incl += t;
    }
    int excl = incl - s;
    int run = excl;
#pragma unroll
    for (int q = 0; q < 4; q++) {
        if (base + q < NB) g_off0[(base + q) * N_EXP + e] = run;
        run += v[q];
    }
    int total0 = __shfl_sync(0xffffffffu, incl, 31);

#pragma unroll
    for (int q = 0; q < 4; q++)
        v[q] = (base + q < NB) ? g_hist1[(base + q) * N_EXP + e] : 0;
    s = v[0] + v[1] + v[2] + v[3];
    incl = s;
#pragma unroll
    for (int d = 1; d < 32; d <<= 1) {
        int t = __shfl_up_sync(0xffffffffu, incl, d);
        if (lane >= d) incl += t;
    }
    excl = incl - s;
    run = total0 + excl;
#pragma unroll
    for (int q = 0; q < 4; q++) {
        if (base + q < NB) g_off1[(base + q) * N_EXP + e] = run;
        run += v[q];
    }
}

// ---------------- K4: ranks, capacity mask, all outputs ----------------------
__global__ void k_final(int N, int cap, float* __restrict__ out, long out_elems) {
    __shared__ int s1[HB], s2[HB], r0[HB], r1[HB];
    __shared__ float sp1[HB], sp2[HB];
    int tid = threadIdx.x;
    int b = blockIdx.x;
    int n = b * HB + tid;

    s1[tid] = g_top1[n];
    s2[tid] = g_top2[n];
    sp1[tid] = g_p1[n];
    sp2[tid] = g_p2[n];
    __syncthreads();

    if (tid < N_EXP) {
        int e = tid;
        int c = g_off0[b * N_EXP + e];
        for (int i = 0; i < HB; i++)
            if (s1[i] == e) r0[i] = c++;
        c = g_off1[b * N_EXP + e];
        for (int i = 0; i < HB; i++)
            if (s2[i] == e) r1[i] = c++;
    }
    __syncthreads();

    // output layout (float32 elements):
    //   [0, N*128)        final_mask [N,2,64]
    //   [N*128, N*130)    router_probs_masked [N,2]
    //   [N*130, N*132)    top_k_indices [N,2]
    //   [N*132, N*134)    final_rank [N,2]
    //   [N*134]           exp_capacity
    const size_t off_probs = (size_t)N * 128;
    const size_t off_idx   = off_probs + (size_t)N * 2;
    const size_t off_rank  = off_idx + (size_t)N * 2;
    const size_t off_cap   = off_rank + (size_t)N * 2;

    int t1 = s1[tid], t2 = s2[tid];
    int rr0 = r0[tid], rr1 = r1[tid];
    bool k0 = rr0 < cap, k1 = rr1 < cap;

    size_t p;
    p = off_idx + (size_t)n * 2;
    if (p + 1 < (size_t)out_elems) { out[p] = (float)t1; out[p + 1] = (float)t2; }
    p = off_rank + (size_t)n * 2;
    if (p + 1 < (size_t)out_elems) { out[p] = (float)rr0; out[p + 1] = (float)rr1; }
    p = off_probs + (size_t)n * 2;
    if (p + 1 < (size_t)out_elems) {
        out[p]     = k0 ? sp1[tid] : 0.0f;
        out[p + 1] = k1 ? sp2[tid] : 0.0f;
    }
    if (b == 0 && tid == 0 && off_cap < (size_t)out_elems) out[off_cap] = (float)cap;

    // mask slab: coalesced — for each token row i, thread writes column tid
    for (int i = 0; i < HB; i++) {
        size_t tn = (size_t)(b * HB + i);
        size_t base = tn * 128;
        float v;
        if (tid < 64)
            v = (s1[i] == tid && r0[i] < cap) ? 1.0f : 0.0f;
        else
            v = (s2[i] == (tid - 64) && r1[i] < cap) ? 1.0f : 0.0f;
        size_t pos = base + tid;
        if (pos < (size_t)out_elems) out[pos] = v;
    }
}

// ---------------- launch ------------------------------------------------------
extern "C" void kernel_launch(void* const* d_in, const int* in_sizes, int n_in,
                              void* d_out, int out_size) {
    const float* x = (const float*)d_in[0];
    const float* w = (const float*)d_in[1];
    int N = in_sizes[0] / C_DIM;              // 16384
    if (N > MAX_N) N = MAX_N;

    int cap = (int)((2.0 * 2.0 * (double)N) / 64.0);
    if (cap < 4) cap = 4;

    int NB = N / HB;

    k_gemm<<<N / TM, 256>>>(x, w);
    k_hist<<<NB, HB>>>();
    k_prefix<<<N_EXP, 32>>>(NB);
    k_final<<<NB, HB>>>(N, cap, (float*)d_out, (long)out_size);
}

// round 4
// speedup vs baseline: 3.1303x; 3.1303x over previous
#include <cuda_runtime.h>
#include <cuda_bf16.h>
#include <math.h>
#include <stdint.h>

// Problem constants
#define C_DIM 2048
#define N_EXP 64
#define MAX_N 16384
#define HB 128           // tokens per histogram/rank block
#define MAX_NB (MAX_N / HB)

#define TM 64
#define BK 64

// ---------------- scratch (device globals; no allocation allowed) -------------
__device__ int   g_top1[MAX_N];
__device__ int   g_top2[MAX_N];
__device__ float g_p1[MAX_N];
__device__ float g_p2[MAX_N];
__device__ int   g_hist0[MAX_NB * N_EXP];
__device__ int   g_hist1[MAX_NB * N_EXP];
__device__ int   g_off0[MAX_NB * N_EXP];
__device__ int   g_off1[MAX_NB * N_EXP];

__device__ __forceinline__ uint32_t cvta_smem(const void* p) {
    uint32_t a;
    asm("{ .reg .u64 t; cvta.to.shared.u64 t, %1; cvt.u32.u64 %0, t; }"
        : "=r"(a) : "l"(p));
    return a;
}

// ---------------- K1: gating GEMM + fused top-2/softmax ----------------------
// Block: 64 tokens x 64 experts, BK=64, 256 threads, thread tile 4 tokens x 4 experts.
// Packed-f32x2 operands, conflict-free by construction:
//   xs2[t][k]      = (x[t][k], x[t][k])        t-major; consumer loads broadcast
//   ws2k[k][psw]   = (w[2p][k], w[2p+1][k])    K-MAJOR; pair index XOR-swizzled
//                    psw = p ^ (k & 0x1E)      (even XOR: pairs stay 16B-adjacent)
union GemmSmem {
    struct {
        float2 xs2[TM][BK];           // 32 KB
        float2 ws2k[BK][N_EXP / 2];   // 16 KB, k-major
    } g;
    float lg[TM][N_EXP + 1];          // logits staging for fused top-2
};

__global__ __launch_bounds__(256) void k_gemm(const float* __restrict__ x,
                                              const float* __restrict__ w) {
    __shared__ GemmSmem sm;

    const int tid = threadIdx.x;
    const int block_t0 = blockIdx.x * TM;
    const int tg = tid >> 4;          // 0..15
    const int eg = tid & 15;          // 0..15
    const int t0 = tg << 2;           // token offset within tile
    const int p0 = eg << 1;           // expert-pair offset (experts 2*p0 .. 2*p0+3)

    unsigned long long acc[4][2];     // [token][expert-pair] packed f32x2
#pragma unroll
    for (int i = 0; i < 4; i++) { acc[i][0] = 0ull; acc[i][1] = 0ull; }

    const uint32_t xbase = cvta_smem(&sm.g.xs2[t0][0]);
    const uint32_t wbase = cvta_smem(&sm.g.ws2k[0][0]);

    for (int k0 = 0; k0 < C_DIM; k0 += BK) {
        // ---- x tile: 64 rows x 16 float4 groups = 1024, 4 per thread ----
#pragma unroll
        for (int l = 0; l < 4; l++) {
            int idx = tid + l * 256;
            int r   = idx >> 4;
            int c4  = idx & 15;
            float4 v = *(const float4*)&x[(size_t)(block_t0 + r) * C_DIM + k0 + (c4 << 2)];
            float4* dst = (float4*)&sm.g.xs2[r][c4 << 2];
            dst[0] = make_float4(v.x, v.x, v.y, v.y);
            dst[1] = make_float4(v.z, v.z, v.w, v.w);
        }
        // ---- w tile: 32 pairs x 16 float4 groups = 512, 2 per thread ----
        // gmem reads coalesced (half-warp covers 256B of one expert row);
        // stores scattered to k-major rows with pair-XOR swizzle.
#pragma unroll
        for (int l = 0; l < 2; l++) {
            int idx = tid + l * 256;
            int p   = idx >> 4;               // pair 0..31
            int c4  = idx & 15;               // float4 group in k
            float4 a = *(const float4*)&w[(size_t)(2 * p)     * C_DIM + k0 + (c4 << 2)];
            float4 b = *(const float4*)&w[(size_t)(2 * p + 1) * C_DIM + k0 + (c4 << 2)];
            int kb = c4 << 2;
            sm.g.ws2k[kb + 0][p ^ ((kb + 0) & 0x1E)] = make_float2(a.x, b.x);
            sm.g.ws2k[kb + 1][p ^ ((kb + 1) & 0x1E)] = make_float2(a.y, b.y);
            sm.g.ws2k[kb + 2][p ^ ((kb + 2) & 0x1E)] = make_float2(a.z, b.z);
            sm.g.ws2k[kb + 3][p ^ ((kb + 3) & 0x1E)] = make_float2(a.w, b.w);
        }
        __syncthreads();

        // ---- packed FFMA2 inner loop: 2 k-steps per iteration ----
        // per iter: 4 x-loads (broadcast) + 2 w-loads (conflict-free) + 16 FFMA2
#pragma unroll 4
        for (int kk = 0; kk < BK; kk += 2) {
            unsigned long long xa0[4], xa1[4];
#pragma unroll
            for (int i = 0; i < 4; i++) {
                uint32_t addr = xbase + i * (BK * 8) + kk * 8;
                asm("ld.shared.v2.b64 {%0, %1}, [%2];"
                    : "=l"(xa0[i]), "=l"(xa1[i]) : "r"(addr));
            }
            // w pairs (p0, p0+1) at k=kk and k=kk+1
            unsigned long long w0a, w0b, w1a, w1b;
            {
                uint32_t a0 = wbase + (uint32_t)(kk    ) * 256u + (uint32_t)((p0 ^ ((kk    ) & 0x1E)) * 8);
                uint32_t a1 = wbase + (uint32_t)(kk + 1) * 256u + (uint32_t)((p0 ^ ((kk + 1) & 0x1E)) * 8);
                asm("ld.shared.v2.b64 {%0, %1}, [%2];" : "=l"(w0a), "=l"(w0b) : "r"(a0));
                asm("ld.shared.v2.b64 {%0, %1}, [%2];" : "=l"(w1a), "=l"(w1b) : "r"(a1));
            }
#pragma unroll
            for (int i = 0; i < 4; i++) {
                asm("fma.rn.f32x2 %0, %1, %2, %0;" : "+l"(acc[i][0]) : "l"(xa0[i]), "l"(w0a));
                asm("fma.rn.f32x2 %0, %1, %2, %0;" : "+l"(acc[i][1]) : "l"(xa0[i]), "l"(w0b));
                asm("fma.rn.f32x2 %0, %1, %2, %0;" : "+l"(acc[i][0]) : "l"(xa1[i]), "l"(w1a));
                asm("fma.rn.f32x2 %0, %1, %2, %0;" : "+l"(acc[i][1]) : "l"(xa1[i]), "l"(w1b));
            }
        }
        __syncthreads();
    }

    // ---- epilogue: stage logits in smem, fused top-2 + softmax ----
#pragma unroll
    for (int i = 0; i < 4; i++) {
#pragma unroll
        for (int j = 0; j < 2; j++) {
            unsigned long long v = acc[i][j];
            float lo = __uint_as_float((unsigned int)(v & 0xffffffffull));
            float hi = __uint_as_float((unsigned int)(v >> 32));
            int e = (p0 + j) * 2;
            sm.lg[t0 + i][e]     = lo;
            sm.lg[t0 + i][e + 1] = hi;
        }
    }
    __syncthreads();

    if (tid < TM) {
        const float* row = &sm.lg[tid][0];
        float b1 = -INFINITY, b2 = -INFINITY;
        int i1 = 0, i2 = 0;
#pragma unroll 8
        for (int e = 0; e < N_EXP; e++) {
            float v = row[e];
            if (v > b1) { b2 = b1; i2 = i1; b1 = v; i1 = e; }
            else if (v > b2) { b2 = v; i2 = e; }
        }
        float e2 = expf(b2 - b1);
        float inv = 1.0f / (1.0f + e2);
        int n = block_t0 + tid;
        g_top1[n] = i1; g_top2[n] = i2;
        g_p1[n] = inv;
        g_p2[n] = e2 * inv;
    }
}

// ---------------- K2: per-block expert histograms ----------------------------
__global__ void k_hist() {
    __shared__ int h0[N_EXP], h1[N_EXP];
    int tid = threadIdx.x;
    int b = blockIdx.x;
    if (tid < N_EXP) { h0[tid] = 0; h1[tid] = 0; }
    __syncthreads();
    int n = b * HB + tid;
    atomicAdd(&h0[g_top1[n]], 1);
    atomicAdd(&h1[g_top2[n]], 1);
    __syncthreads();
    if (tid < N_EXP) {
        g_hist0[b * N_EXP + tid] = h0[tid];
        g_hist1[b * N_EXP + tid] = h1[tid];
    }
}

// ---------------- K3: parallel per-expert prefix over blocks -----------------
__global__ void k_prefix(int NB) {
    const int e = blockIdx.x;
    const int lane = threadIdx.x;
    const int base = lane * 4;

    int v[4];
#pragma unroll
    for (int q = 0; q < 4; q++)
        v[q] = (base + q < NB) ? g_hist0[(base + q) * N_EXP + e] : 0;
    int s = v[0] + v[1] + v[2] + v[3];
    int incl = s;
#pragma unroll
    for (int d = 1; d < 32; d <<= 1) {
        int t = __shfl_up_sync(0xffffffffu, incl, d);
        if (lane >= d) incl += t;
    }
    int run = incl - s;
#pragma unroll
    for (int q = 0; q < 4; q++) {
        if (base + q < NB) g_off0[(base + q) * N_EXP + e] = run;
        run += v[q];
    }
    int total0 = __shfl_sync(0xffffffffu, incl, 31);

#pragma unroll
    for (int q = 0; q < 4; q++)
        v[q] = (base + q < NB) ? g_hist1[(base + q) * N_EXP + e] : 0;
    s = v[0] + v[1] + v[2] + v[3];
    incl = s;
#pragma unroll
    for (int d = 1; d < 32; d <<= 1) {
        int t = __shfl_up_sync(0xffffffffu, incl, d);
        if (lane >= d) incl += t;
    }
    run = total0 + (incl - s);
#pragma unroll
    for (int q = 0; q < 4; q++) {
        if (base + q < NB) g_off1[(base + q) * N_EXP + e] = run;
        run += v[q];
    }
}

// ---------------- K4: ranks, capacity mask, all outputs ----------------------
__global__ void k_final(int N, int cap, float* __restrict__ out, long out_elems) {
    __shared__ int s1[HB], s2[HB], r0[HB], r1[HB];
    __shared__ float sp1[HB], sp2[HB];
    int tid = threadIdx.x;
    int b = blockIdx.x;
    int n = b * HB + tid;

    s1[tid] = g_top1[n];
    s2[tid] = g_top2[n];
    sp1[tid] = g_p1[n];
    sp2[tid] = g_p2[n];
    __syncthreads();

    if (tid < N_EXP) {
        int e = tid;
        int c = g_off0[b * N_EXP + e];
        for (int i = 0; i < HB; i++)
            if (s1[i] == e) r0[i] = c++;
        c = g_off1[b * N_EXP + e];
        for (int i = 0; i < HB; i++)
            if (s2[i] == e) r1[i] = c++;
    }
    __syncthreads();

    // output layout (float32 elements):
    //   [0, N*128)        final_mask [N,2,64]
    //   [N*128, N*130)    router_probs_masked [N,2]
    //   [N*130, N*132)    top_k_indices [N,2]
    //   [N*132, N*134)    final_rank [N,2]
    //   [N*134]           exp_capacity
    const size_t off_probs = (size_t)N * 128;
    const size_t off_idx   = off_probs + (size_t)N * 2;
    const size_t off_rank  = off_idx + (size_t)N * 2;
    const size_t off_cap   = off_rank + (size_t)N * 2;

    int t1 = s1[tid], t2 = s2[tid];
    int rr0 = r0[tid], rr1 = r1[tid];
    bool k0 = rr0 < cap, k1 = rr1 < cap;

    size_t p;
    p = off_idx + (size_t)n * 2;
    if (p + 1 < (size_t)out_elems) { out[p] = (float)t1; out[p + 1] = (float)t2; }
    p = off_rank + (size_t)n * 2;
    if (p + 1 < (size_t)out_elems) { out[p] = (float)rr0; out[p + 1] = (float)rr1; }
    p = off_probs + (size_t)n * 2;
    if (p + 1 < (size_t)out_elems) {
        out[p]     = k0 ? sp1[tid] : 0.0f;
        out[p + 1] = k1 ? sp2[tid] : 0.0f;
    }
    if (b == 0 && tid == 0 && off_cap < (size_t)out_elems) out[off_cap] = (float)cap;

    // mask slab: coalesced — for each token row i, thread writes column tid
    for (int i = 0; i < HB; i++) {
        size_t tn = (size_t)(b * HB + i);
        size_t base = tn * 128;
        float v;
        if (tid < 64)
            v = (s1[i] == tid && r0[i] < cap) ? 1.0f : 0.0f;
        else
            v = (s2[i] == (tid - 64) && r1[i] < cap) ? 1.0f : 0.0f;
        size_t pos = base + tid;
        if (pos < (size_t)out_elems) out[pos] = v;
    }
}

// ---------------- launch ------------------------------------------------------
extern "C" void kernel_launch(void* const* d_in, const int* in_sizes, int n_in,
                              void* d_out, int out_size) {
    const float* x = (const float*)d_in[0];
    const float* w = (const float*)d_in[1];
    int N = in_sizes[0] / C_DIM;              // 16384
    if (N > MAX_N) N = MAX_N;

    int cap = (int)((2.0 * 2.0 * (double)N) / 64.0);
    if (cap < 4) cap = 4;

    int NB = N / HB;

    k_gemm<<<N / TM, 256>>>(x, w);
    k_hist<<<NB, HB>>>();
    k_prefix<<<N_EXP, 32>>>(NB);
    k_final<<<NB, HB>>>(N, cap, (float*)d_out, (long)out_size);
}

// round 5
// speedup vs baseline: 4.1141x; 1.3143x over previous
#include <cuda_runtime.h>
#include <cuda_bf16.h>
#include <math.h>
#include <stdint.h>

// Problem constants
#define C_DIM 2048
#define N_EXP 64
#define MAX_N 16384
#define HB 64            // tokens per tile/hist/rank block (== GEMM tile)
#define MAX_NB (MAX_N / HB)

#define TM 64
#define BK 64

// ---------------- scratch (device globals; no allocation allowed) -------------
__device__ int   g_top1[MAX_N];
__device__ int   g_top2[MAX_N];
__device__ float g_p1[MAX_N];
__device__ float g_p2[MAX_N];
__device__ int   g_hist0[MAX_NB * N_EXP];
__device__ int   g_hist1[MAX_NB * N_EXP];
__device__ int   g_off0[MAX_NB * N_EXP];
__device__ int   g_off1[MAX_NB * N_EXP];

// ---------------- K1: gating GEMM + fused top-2/softmax/histogram -----------
// Block: 64 tokens x 64 experts, BK=64, 256 threads, 4x4 thread tile.
// Scalar FFMA path (measured at the FFMA-3reg issue roofline).
union GemmSmem {
    struct {
        float xs[TM][BK + 4];      // padded rows (17.4 KB)
        float ws[N_EXP][BK];       // XOR-swizzled at float4 granularity (16 KB)
    } g;
    float lg[TM][N_EXP + 1];       // logits staging for fused top-2 (16.6 KB)
};

__global__ __launch_bounds__(256) void k_gemm(const float* __restrict__ x,
                                              const float* __restrict__ w) {
    __shared__ GemmSmem sm;
    __shared__ int h0[N_EXP], h1[N_EXP];

    const int tid = threadIdx.x;
    const int b = blockIdx.x;
    const int block_t0 = b * TM;
    const int tg = tid >> 4;          // 0..15
    const int eg = tid & 15;          // 0..15
    const int t0 = tg << 2;
    const int e0 = eg << 2;

    float acc[4][4];
#pragma unroll
    for (int i = 0; i < 4; i++)
#pragma unroll
        for (int j = 0; j < 4; j++) acc[i][j] = 0.0f;

    for (int k0 = 0; k0 < C_DIM; k0 += BK) {
        // cooperative tile load: 64x64 floats each = 1024 float4, 4 per thread
#pragma unroll
        for (int l = 0; l < 4; l++) {
            int idx = tid + l * 256;          // 0..1023
            int r   = idx >> 4;               // row 0..63
            int c4  = idx & 15;               // float4 column 0..15
            float4 xv = *(const float4*)&x[(size_t)(block_t0 + r) * C_DIM + k0 + (c4 << 2)];
            *(float4*)&sm.g.xs[r][c4 << 2] = xv;
            float4 wv = *(const float4*)&w[(size_t)r * C_DIM + k0 + (c4 << 2)];
            int sc4 = c4 ^ ((r >> 2) & 7);    // bank swizzle
            *(float4*)&sm.g.ws[r][sc4 << 2] = wv;
        }
        __syncthreads();

#pragma unroll 4
        for (int kk = 0; kk < BK; kk += 4) {
            float4 xv[4], wv[4];
#pragma unroll
            for (int i = 0; i < 4; i++)
                xv[i] = *(const float4*)&sm.g.xs[t0 + i][kk];
#pragma unroll
            for (int j = 0; j < 4; j++) {
                int e = e0 + j;
                int sc4 = (kk >> 2) ^ ((e >> 2) & 7);
                wv[j] = *(const float4*)&sm.g.ws[e][sc4 << 2];
            }
#pragma unroll
            for (int i = 0; i < 4; i++) {
#pragma unroll
                for (int j = 0; j < 4; j++) {
                    acc[i][j] += xv[i].x * wv[j].x;
                    acc[i][j] += xv[i].y * wv[j].y;
                    acc[i][j] += xv[i].z * wv[j].z;
                    acc[i][j] += xv[i].w * wv[j].w;
                }
            }
        }
        __syncthreads();
    }

    // ---- stage logits to smem (union over the gemm tiles) ----
#pragma unroll
    for (int i = 0; i < 4; i++)
#pragma unroll
        for (int j = 0; j < 4; j++)
            sm.lg[t0 + i][e0 + j] = acc[i][j];
    if (tid < N_EXP) { h0[tid] = 0; h1[tid] = 0; }
    __syncthreads();

    // ---- fused top-2 + softmax + per-tile histogram ----
    if (tid < TM) {
        const float* row = &sm.lg[tid][0];
        float b1 = -INFINITY, b2 = -INFINITY;
        int i1 = 0, i2 = 0;
#pragma unroll 8
        for (int e = 0; e < N_EXP; e++) {
            float v = row[e];
            if (v > b1) { b2 = b1; i2 = i1; b1 = v; i1 = e; }
            else if (v > b2) { b2 = v; i2 = e; }
        }
        float e2 = expf(b2 - b1);
        float inv = 1.0f / (1.0f + e2);
        int n = block_t0 + tid;
        g_top1[n] = i1; g_top2[n] = i2;
        g_p1[n] = inv;
        g_p2[n] = e2 * inv;
        atomicAdd(&h0[i1], 1);
        atomicAdd(&h1[i2], 1);
    }
    __syncthreads();
    if (tid < N_EXP) {
        g_hist0[b * N_EXP + tid] = h0[tid];
        g_hist1[b * N_EXP + tid] = h1[tid];
    }
}

// ---------------- K2: parallel per-expert prefix over tiles ------------------
// grid = 64 blocks (one expert each), 32 threads; lane L owns 8 tile-hists.
#define QPT (MAX_NB / 32)   // 8

__global__ void k_prefix(int NB) {
    const int e = blockIdx.x;
    const int lane = threadIdx.x;
    const int base = lane * QPT;

    int v[QPT];
#pragma unroll
    for (int q = 0; q < QPT; q++)
        v[q] = (base + q < NB) ? g_hist0[(base + q) * N_EXP + e] : 0;
    int s = 0;
#pragma unroll
    for (int q = 0; q < QPT; q++) s += v[q];
    int incl = s;
#pragma unroll
    for (int d = 1; d < 32; d <<= 1) {
        int t = __shfl_up_sync(0xffffffffu, incl, d);
        if (lane >= d) incl += t;
    }
    int run = incl - s;
#pragma unroll
    for (int q = 0; q < QPT; q++) {
        if (base + q < NB) g_off0[(base + q) * N_EXP + e] = run;
        run += v[q];
    }
    int total0 = __shfl_sync(0xffffffffu, incl, 31);

#pragma unroll
    for (int q = 0; q < QPT; q++)
        v[q] = (base + q < NB) ? g_hist1[(base + q) * N_EXP + e] : 0;
    s = 0;
#pragma unroll
    for (int q = 0; q < QPT; q++) s += v[q];
    incl = s;
#pragma unroll
    for (int d = 1; d < 32; d <<= 1) {
        int t = __shfl_up_sync(0xffffffffu, incl, d);
        if (lane >= d) incl += t;
    }
    run = total0 + (incl - s);
#pragma unroll
    for (int q = 0; q < QPT; q++) {
        if (base + q < NB) g_off1[(base + q) * N_EXP + e] = run;
        run += v[q];
    }
}

// ---------------- K3: ranks via match_any, capacity mask, all outputs --------
// grid = NB blocks, 128 threads. Tokens 0..63 handled by warps 0-1 (full warps).
__global__ void k_final(int N, int cap, float* __restrict__ out, long out_elems) {
    __shared__ int s1[HB], s2[HB], r0[HB], r1[HB];
    __shared__ int wh0[2][N_EXP], wh1[2][N_EXP];
    __shared__ float sp1[HB], sp2[HB];

    const int tid = threadIdx.x;
    const int b = blockIdx.x;
    const int warp = tid >> 5;
    const int lane = tid & 31;
    const int n = b * HB + tid;

    if (tid < 128) {
        (&wh0[0][0])[tid] = 0;
        (&wh1[0][0])[tid] = 0;
    }

    int e1 = 0, e2v = 0, rw0 = 0, rw1 = 0;
    float p1v = 0.f, p2v = 0.f;
    if (tid < HB) {
        e1  = g_top1[n];
        e2v = g_top2[n];
        p1v = g_p1[n];
        p2v = g_p2[n];
        s1[tid] = e1; s2[tid] = e2v;
        sp1[tid] = p1v; sp2[tid] = p2v;
    }
    __syncthreads();

    if (tid < HB) {
        unsigned lt = (1u << lane) - 1u;
        unsigned m0 = __match_any_sync(0xffffffffu, e1);
        rw0 = __popc(m0 & lt);
        if (rw0 == 0) wh0[warp][e1] = __popc(m0);     // group leader writes count
        unsigned m1 = __match_any_sync(0xffffffffu, e2v);
        rw1 = __popc(m1 & lt);
        if (rw1 == 0) wh1[warp][e2v] = __popc(m1);
    }
    __syncthreads();

    // output layout (float32 elements):
    //   [0, N*128)        final_mask [N,2,64]
    //   [N*128, N*130)    router_probs_masked [N,2]
    //   [N*130, N*132)    top_k_indices [N,2]
    //   [N*132, N*134)    final_rank [N,2]
    //   [N*134]           exp_capacity
    const size_t off_probs = (size_t)N * 128;
    const size_t off_idx   = off_probs + (size_t)N * 2;
    const size_t off_rank  = off_idx + (size_t)N * 2;
    const size_t off_cap   = off_rank + (size_t)N * 2;

    if (tid < HB) {
        int rr0 = g_off0[b * N_EXP + e1]  + rw0 + (warp ? wh0[0][e1]  : 0);
        int rr1 = g_off1[b * N_EXP + e2v] + rw1 + (warp ? wh1[0][e2v] : 0);
        r0[tid] = rr0; r1[tid] = rr1;

        size_t p;
        p = off_idx + (size_t)n * 2;
        if (p + 1 < (size_t)out_elems) { out[p] = (float)e1; out[p + 1] = (float)e2v; }
        p = off_rank + (size_t)n * 2;
        if (p + 1 < (size_t)out_elems) { out[p] = (float)rr0; out[p + 1] = (float)rr1; }
        p = off_probs + (size_t)n * 2;
        if (p + 1 < (size_t)out_elems) {
            out[p]     = (rr0 < cap) ? p1v : 0.0f;
            out[p + 1] = (rr1 < cap) ? p2v : 0.0f;
        }
    }
    if (b == 0 && tid == 0 && off_cap < (size_t)out_elems) out[off_cap] = (float)cap;
    __syncthreads();

    // mask slab: coalesced — for each token row i, thread writes column tid
    for (int i = 0; i < HB; i++) {
        size_t tn = (size_t)(b * HB + i);
        size_t base = tn * 128;
        float v;
        if (tid < 64)
            v = (s1[i] == tid && r0[i] < cap) ? 1.0f : 0.0f;
        else
            v = (s2[i] == (tid - 64) && r1[i] < cap) ? 1.0f : 0.0f;
        size_t pos = base + tid;
        if (pos < (size_t)out_elems) out[pos] = v;
    }
}

// ---------------- launch ------------------------------------------------------
extern "C" void kernel_launch(void* const* d_in, const int* in_sizes, int n_in,
                              void* d_out, int out_size) {
    const float* x = (const float*)d_in[0];
    const float* w = (const float*)d_in[1];
    int N = in_sizes[0] / C_DIM;              // 16384
    if (N > MAX_N) N = MAX_N;

    int cap = (int)((2.0 * 2.0 * (double)N) / 64.0);
    if (cap < 4) cap = 4;

    int NB = N / HB;                          // 256

    k_gemm<<<N / TM, 256>>>(x, w);
    k_prefix<<<N_EXP, 32>>>(NB);
    k_final<<<NB, 128>>>(N, cap, (float*)d_out, (long)out_size);
}

// round 7
// speedup vs baseline: 5.3770x; 1.3069x over previous
#include <cuda_runtime.h>
#include <cuda_bf16.h>
#include <math.h>
#include <stdint.h>

// Problem constants
#define C_DIM 2048
#define N_EXP 64
#define MAX_N 16384
#define TMB 128                    // tokens per GEMM block / hist block
#define MAX_NB (MAX_N / TMB)       // 128
#define BKC 64                     // k per chunk (rows of 64 bf16 = 128 B)
#define NCHUNK (C_DIM / BKC)       // 32

// ---------------- scratch (device globals; no allocation allowed) -------------
__device__ int   g_top1[MAX_N];
__device__ int   g_top2[MAX_N];
__device__ float g_p1[MAX_N];
__device__ float g_p2[MAX_N];
__device__ int   g_hist0[MAX_NB * N_EXP];
__device__ int   g_hist1[MAX_NB * N_EXP];
__device__ int   g_off0[MAX_NB * N_EXP];
__device__ int   g_off1[MAX_NB * N_EXP];
__device__ __nv_bfloat16 g_wsp[3][N_EXP * C_DIM];   // w split hi/mid/lo

__device__ __forceinline__ uint32_t cvta_smem(const void* p) {
    uint32_t a;
    asm("{ .reg .u64 t; cvta.to.shared.u64 t, %1; cvt.u32.u64 %0, t; }"
        : "=r"(a) : "l"(p));
    return a;
}

__device__ __forceinline__ uint32_t pack_bf2(__nv_bfloat16 a, __nv_bfloat16 b) {
    uint16_t ua = *(uint16_t*)&a, ub = *(uint16_t*)&b;
    return (uint32_t)ua | ((uint32_t)ub << 16);
}

// ---------------- K0: split w into hi/mid/lo bf16 ----------------------------
__global__ void k_wsplit(const float* __restrict__ w) {
    int e = blockIdx.x;
    int t = threadIdx.x;
#pragma unroll
    for (int i = 0; i < C_DIM / 256; i++) {
        int k = t + i * 256;
        float v = w[(size_t)e * C_DIM + k];
        __nv_bfloat16 h = __float2bfloat16(v);
        float r1 = v - __bfloat162float(h);
        __nv_bfloat16 m = __float2bfloat16(r1);
        float r2 = r1 - __bfloat162float(m);
        __nv_bfloat16 l = __float2bfloat16(r2);
        g_wsp[0][(size_t)e * C_DIM + k] = h;
        g_wsp[1][(size_t)e * C_DIM + k] = m;
        g_wsp[2][(size_t)e * C_DIM + k] = l;
    }
}

// ---------------- K1: HMMA (mma.sync bf16) GEMM + fused top-2/softmax/hist ---
// One block per 128-token tile; 8 warps in a 4(M)x2(N) grid: 32 tok x 32 exp each.
// Smem (dynamic): A: 3 levels x 128 rows x 128B = 48 KB at 0
//                 B: 3 levels x  64 rows x 128B = 24 KB at 49152
#define SM_A_OFF 0
#define SM_B_OFF (3 * 16384)
#define SM_TOTAL (SM_B_OFF + 3 * 8192)

__global__ __launch_bounds__(256, 1)
void k_gemm_mma(const float* __restrict__ x) {
    extern __shared__ char smem[];
    const uint32_t sb = cvta_smem(smem);
    const int tid = threadIdx.x;
    const int wid = tid >> 5;
    const int lane = tid & 31;
    const int b = blockIdx.x;
    const int block_t0 = b * TMB;

    __shared__ int h0[N_EXP], h1[N_EXP];
    if (tid < N_EXP) { h0[tid] = 0; h1[tid] = 0; }

    const int wm = wid >> 1;        // 0..3  -> token rows wm*32
    const int wn = wid & 1;         // 0..1  -> expert cols wn*32
    const int R = wm * 32;
    const int Ecol = wn * 32;

    float acc[2][4][4];
#pragma unroll
    for (int mt = 0; mt < 2; mt++)
#pragma unroll
        for (int nt = 0; nt < 4; nt++)
#pragma unroll
            for (int q = 0; q < 4; q++) acc[mt][nt][q] = 0.0f;

    // ---- prefetch registers ----
    float4 xva[4], xvb[4];
    uint4 wv[2][3];

    auto gload = [&](int c) {
#pragma unroll
        for (int i = 0; i < 4; i++) {
            int u = tid + i * 256;
            int r = u >> 3, cu = u & 7;
            const float* src = x + (size_t)(block_t0 + r) * C_DIM + c * BKC + cu * 8;
            xva[i] = *(const float4*)src;
            xvb[i] = *(const float4*)(src + 4);
        }
#pragma unroll
        for (int i = 0; i < 2; i++) {
            int u = tid + i * 256;
            int e = u >> 3, cu = u & 7;
            size_t s = (size_t)e * C_DIM + c * BKC + cu * 8;
#pragma unroll
            for (int l = 0; l < 3; l++)
                wv[i][l] = *(const uint4*)&g_wsp[l][s];
        }
    };

    auto sstore = [&]() {
#pragma unroll
        for (int i = 0; i < 4; i++) {
            int u = tid + i * 256;
            int r = u >> 3, cu = u & 7;
            float v[8] = {xva[i].x, xva[i].y, xva[i].z, xva[i].w,
                          xvb[i].x, xvb[i].y, xvb[i].z, xvb[i].w};
            uint32_t ph[4], pm[4], pl[4];
#pragma unroll
            for (int j = 0; j < 4; j++) {
                float vA = v[2 * j], vB = v[2 * j + 1];
                __nv_bfloat16 hA = __float2bfloat16(vA);
                float rA = vA - __bfloat162float(hA);
                __nv_bfloat16 mA = __float2bfloat16(rA);
                __nv_bfloat16 lA = __float2bfloat16(rA - __bfloat162float(mA));
                __nv_bfloat16 hB = __float2bfloat16(vB);
                float rB = vB - __bfloat162float(hB);
                __nv_bfloat16 mB = __float2bfloat16(rB);
                __nv_bfloat16 lB = __float2bfloat16(rB - __bfloat162float(mB));
                ph[j] = pack_bf2(hA, hB);
                pm[j] = pack_bf2(mA, mB);
                pl[j] = pack_bf2(lA, lB);
            }
            uint32_t dst = (uint32_t)(r * 128 + ((cu ^ (r & 7)) << 4));
            *(uint4*)(smem + SM_A_OFF + 0 * 16384 + dst) = make_uint4(ph[0], ph[1], ph[2], ph[3]);
            *(uint4*)(smem + SM_A_OFF + 1 * 16384 + dst) = make_uint4(pm[0], pm[1], pm[2], pm[3]);
            *(uint4*)(smem + SM_A_OFF + 2 * 16384 + dst) = make_uint4(pl[0], pl[1], pl[2], pl[3]);
        }
#pragma unroll
        for (int i = 0; i < 2; i++) {
            int u = tid + i * 256;
            int e = u >> 3, cu = u & 7;
            uint32_t dst = (uint32_t)(e * 128 + ((cu ^ (e & 7)) << 4));
#pragma unroll
            for (int l = 0; l < 3; l++)
                *(uint4*)(smem + SM_B_OFF + l * 8192 + dst) = wv[i][l];
        }
    };

    gload(0);
    sstore();
    __syncthreads();

    for (int c = 0; c < NCHUNK; c++) {
        if (c + 1 < NCHUNK) gload(c + 1);   // overlaps with MMA below

        // 6 split terms: (a_level, b_level)
        const int ta[6] = {0, 0, 1, 0, 1, 2};
        const int tb[6] = {0, 1, 0, 2, 1, 0};
#pragma unroll
        for (int t = 0; t < 6; t++) {
            uint32_t abase = sb + SM_A_OFF + ta[t] * 16384;
            uint32_t bbase = sb + SM_B_OFF + tb[t] * 8192;
#pragma unroll
            for (int ks = 0; ks < 4; ks++) {
                uint32_t ra[2][4];
#pragma unroll
                for (int mt = 0; mt < 2; mt++) {
                    int row = R + mt * 16 + (lane & 15);
                    int unit = ks * 2 + (lane >> 4);
                    uint32_t addr = abase + row * 128 + ((unit ^ (row & 7)) << 4);
                    asm volatile(
                        "ldmatrix.sync.aligned.m8n8.x4.shared.b16 {%0,%1,%2,%3}, [%4];"
                        : "=r"(ra[mt][0]), "=r"(ra[mt][1]), "=r"(ra[mt][2]), "=r"(ra[mt][3])
                        : "r"(addr));
                }
                uint32_t rb[4][2];
#pragma unroll
                for (int nt = 0; nt < 4; nt++) {
                    int n = Ecol + nt * 8 + (lane & 7);
                    int unit = ks * 2 + ((lane >> 3) & 1);
                    uint32_t addr = bbase + n * 128 + ((unit ^ (n & 7)) << 4);
                    asm volatile(
                        "ldmatrix.sync.aligned.m8n8.x2.shared.b16 {%0,%1}, [%2];"
                        : "=r"(rb[nt][0]), "=r"(rb[nt][1])
                        : "r"(addr));
                }
#pragma unroll
                for (int mt = 0; mt < 2; mt++)
#pragma unroll
                    for (int nt = 0; nt < 4; nt++) {
                        asm volatile(
                            "mma.sync.aligned.m16n8k16.row.col.f32.bf16.bf16.f32 "
                            "{%0,%1,%2,%3}, {%4,%5,%6,%7}, {%8,%9}, {%0,%1,%2,%3};"
                            : "+f"(acc[mt][nt][0]), "+f"(acc[mt][nt][1]),
                              "+f"(acc[mt][nt][2]), "+f"(acc[mt][nt][3])
                            : "r"(ra[mt][0]), "r"(ra[mt][1]), "r"(ra[mt][2]), "r"(ra[mt][3]),
                              "r"(rb[nt][0]), "r"(rb[nt][1]));
                    }
            }
        }
        __syncthreads();
        if (c + 1 < NCHUNK) {
            sstore();
            __syncthreads();
        }
    }

    // ---- epilogue: stage logits (reuse A smem region), top-2 + softmax + hist
    float* lg = (float*)smem;            // [128][65]
    const int LGS = 65;
#pragma unroll
    for (int mt = 0; mt < 2; mt++)
#pragma unroll
        for (int nt = 0; nt < 4; nt++) {
            int r0 = R + mt * 16 + (lane >> 2);
            int c0 = Ecol + nt * 8 + (lane & 3) * 2;
            lg[r0 * LGS + c0]           = acc[mt][nt][0];
            lg[r0 * LGS + c0 + 1]       = acc[mt][nt][1];
            lg[(r0 + 8) * LGS + c0]     = acc[mt][nt][2];
            lg[(r0 + 8) * LGS + c0 + 1] = acc[mt][nt][3];
        }
    __syncthreads();

    if (tid < TMB) {
        const float* row = &lg[tid * LGS];
        float b1 = -INFINITY, b2 = -INFINITY;
        int i1 = 0, i2 = 0;
#pragma unroll 8
        for (int e = 0; e < N_EXP; e++) {
            float v = row[e];
            if (v > b1) { b2 = b1; i2 = i1; b1 = v; i1 = e; }
            else if (v > b2) { b2 = v; i2 = e; }
        }
        float e2 = expf(b2 - b1);
        float inv = 1.0f / (1.0f + e2);
        int n = block_t0 + tid;
        g_top1[n] = i1; g_top2[n] = i2;
        g_p1[n] = inv;  g_p2[n] = e2 * inv;
        atomicAdd(&h0[i1], 1);
        atomicAdd(&h1[i2], 1);
    }
    __syncthreads();
    if (tid < N_EXP) {
        g_hist0[b * N_EXP + tid] = h0[tid];
        g_hist1[b * N_EXP + tid] = h1[tid];
    }
}

// ---------------- K2: parallel per-expert prefix over tiles ------------------
#define QPT (MAX_NB / 32)   // 4

__global__ void k_prefix(int NB) {
    const int e = blockIdx.x;
    const int lane = threadIdx.x;
    const int base = lane * QPT;

    int v[QPT];
#pragma unroll
    for (int q = 0; q < QPT; q++)
        v[q] = (base + q < NB) ? g_hist0[(base + q) * N_EXP + e] : 0;
    int s = 0;
#pragma unroll
    for (int q = 0; q < QPT; q++) s += v[q];
    int incl = s;
#pragma unroll
    for (int d = 1; d < 32; d <<= 1) {
        int t = __shfl_up_sync(0xffffffffu, incl, d);
        if (lane >= d) incl += t;
    }
    int run = incl - s;
#pragma unroll
    for (int q = 0; q < QPT; q++) {
        if (base + q < NB) g_off0[(base + q) * N_EXP + e] = run;
        run += v[q];
    }
    int total0 = __shfl_sync(0xffffffffu, incl, 31);

#pragma unroll
    for (int q = 0; q < QPT; q++)
        v[q] = (base + q < NB) ? g_hist1[(base + q) * N_EXP + e] : 0;
    s = 0;
#pragma unroll
    for (int q = 0; q < QPT; q++) s += v[q];
    incl = s;
#pragma unroll
    for (int d = 1; d < 32; d <<= 1) {
        int t = __shfl_up_sync(0xffffffffu, incl, d);
        if (lane >= d) incl += t;
    }
    run = total0 + (incl - s);
#pragma unroll
    for (int q = 0; q < QPT; q++) {
        if (base + q < NB) g_off1[(base + q) * N_EXP + e] = run;
        run += v[q];
    }
}

// ---------------- K3: ranks via match_any, capacity mask, all outputs --------
__global__ void k_final(int N, int cap, float* __restrict__ out, long out_elems) {
    __shared__ int s1[TMB], s2[TMB], r0[TMB], r1[TMB];
    __shared__ int wh0[4][N_EXP], wh1[4][N_EXP];

    const int tid = threadIdx.x;
    const int b = blockIdx.x;
    const int warp = tid >> 5;
    const int lane = tid & 31;
    const int n = b * TMB + tid;

#pragma unroll
    for (int i = 0; i < 2; i++) {
        (&wh0[0][0])[tid + i * 128] = 0;
        (&wh1[0][0])[tid + i * 128] = 0;
    }

    int e1  = g_top1[n];
    int e2v = g_top2[n];
    float p1v = g_p1[n];
    float p2v = g_p2[n];
    s1[tid] = e1; s2[tid] = e2v;
    __syncthreads();

    unsigned lt = (1u << lane) - 1u;
    unsigned m0 = __match_any_sync(0xffffffffu, e1);
    int rw0 = __popc(m0 & lt);
    if (rw0 == 0) wh0[warp][e1] = __popc(m0);
    unsigned m1 = __match_any_sync(0xffffffffu, e2v);
    int rw1 = __popc(m1 & lt);
    if (rw1 == 0) wh1[warp][e2v] = __popc(m1);
    __syncthreads();

    int add0 = 0, add1 = 0;
#pragma unroll
    for (int w = 0; w < 3; w++) {
        if (w < warp) { add0 += wh0[w][e1]; add1 += wh1[w][e2v]; }
    }
    int rr0 = g_off0[b * N_EXP + e1]  + rw0 + add0;
    int rr1 = g_off1[b * N_EXP + e2v] + rw1 + add1;
    r0[tid] = rr0; r1[tid] = rr1;

    // output layout (float32 elements):
    //   [0, N*128) mask | [N*128,+2N) probs | [+2N) idx | [+2N) rank | [1] cap
    const size_t off_probs = (size_t)N * 128;
    const size_t off_idx   = off_probs + (size_t)N * 2;
    const size_t off_rank  = off_idx + (size_t)N * 2;
    const size_t off_cap   = off_rank + (size_t)N * 2;

    size_t p;
    p = off_idx + (size_t)n * 2;
    if (p + 1 < (size_t)out_elems) { out[p] = (float)e1; out[p + 1] = (float)e2v; }
    p = off_rank + (size_t)n * 2;
    if (p + 1 < (size_t)out_elems) { out[p] = (float)rr0; out[p + 1] = (float)rr1; }
    p = off_probs + (size_t)n * 2;
    if (p + 1 < (size_t)out_elems) {
        out[p]     = (rr0 < cap) ? p1v : 0.0f;
        out[p + 1] = (rr1 < cap) ? p2v : 0.0f;
    }
    if (b == 0 && tid == 0 && off_cap < (size_t)out_elems) out[off_cap] = (float)cap;
    __syncthreads();

    // mask slab: lane writes float4 (4 expert cols) of one token row
    const int e_base = lane * 4;
    for (int i = warp; i < TMB; i += 4) {
        float4 v;
        if (lane < 16) {
            int s = s1[i]; bool ok = r0[i] < cap;
            v.x = (ok && s == e_base + 0) ? 1.0f : 0.0f;
            v.y = (ok && s == e_base + 1) ? 1.0f : 0.0f;
            v.z = (ok && s == e_base + 2) ? 1.0f : 0.0f;
            v.w = (ok && s == e_base + 3) ? 1.0f : 0.0f;
        } else {
            int s = s2[i] + 64; bool ok = r1[i] < cap;
            v.x = (ok && s == e_base + 0) ? 1.0f : 0.0f;
            v.y = (ok && s == e_base + 1) ? 1.0f : 0.0f;
            v.z = (ok && s == e_base + 2) ? 1.0f : 0.0f;
            v.w = (ok && s == e_base + 3) ? 1.0f : 0.0f;
        }
        size_t pos = (size_t)(b * TMB + i) * 128 + e_base;
        if (pos + 3 < (size_t)out_elems) *(float4*)&out[pos] = v;
    }
}

// ---------------- launch ------------------------------------------------------
extern "C" void kernel_launch(void* const* d_in, const int* in_sizes, int n_in,
                              void* d_out, int out_size) {
    const float* x = (const float*)d_in[0];
    const float* w = (const float*)d_in[1];
    int N = in_sizes[0] / C_DIM;              // 16384
    if (N > MAX_N) N = MAX_N;

    int cap = (int)((2.0 * 2.0 * (double)N) / 64.0);
    if (cap < 4) cap = 4;

    int NB = N / TMB;                         // 128

    cudaFuncSetAttribute(k_gemm_mma, cudaFuncAttributeMaxDynamicSharedMemorySize, SM_TOTAL);

    k_wsplit<<<N_EXP, 256>>>(w);
    k_gemm_mma<<<NB, 256, SM_TOTAL>>>(x);
    k_prefix<<<N_EXP, 32>>>(NB);
    k_final<<<NB, 128>>>(N, cap, (float*)d_out, (long)out_size);
}

// round 8
// speedup vs baseline: 5.5978x; 1.0411x over previous
#include <cuda_runtime.h>
#include <cuda_bf16.h>
#include <math.h>
#include <stdint.h>

// Problem constants
#define C_DIM 2048
#define N_EXP 64
#define MAX_N 16384
#define TMB 128                    // tokens per GEMM block / hist block
#define MAX_NB (MAX_N / TMB)       // 128
#define BKC 64                     // k per chunk (rows of 64 bf16 = 128 B)
#define NCHUNK (C_DIM / BKC)       // 32

// ---------------- scratch (device globals; no allocation allowed) -------------
__device__ int   g_top1[MAX_N];
__device__ int   g_top2[MAX_N];
__device__ float g_p1[MAX_N];
__device__ float g_p2[MAX_N];
__device__ int   g_hist0[MAX_NB * N_EXP];
__device__ int   g_hist1[MAX_NB * N_EXP];
__device__ int   g_off0[MAX_NB * N_EXP];
__device__ int   g_off1[MAX_NB * N_EXP];
__device__ __nv_bfloat16 g_wsp[3][N_EXP * C_DIM];   // w split hi/mid/lo

__device__ __forceinline__ uint32_t cvta_smem(const void* p) {
    uint32_t a;
    asm("{ .reg .u64 t; cvta.to.shared.u64 t, %1; cvt.u32.u64 %0, t; }"
        : "=r"(a) : "l"(p));
    return a;
}

__device__ __forceinline__ uint32_t pack_bf2(__nv_bfloat16 a, __nv_bfloat16 b) {
    uint16_t ua = *(uint16_t*)&a, ub = *(uint16_t*)&b;
    return (uint32_t)ua | ((uint32_t)ub << 16);
}

// ---------------- K0: split w into hi/mid/lo bf16 ----------------------------
__global__ void k_wsplit(const float* __restrict__ w) {
    int e = blockIdx.x;
    int t = threadIdx.x;
#pragma unroll
    for (int i = 0; i < C_DIM / 256; i++) {
        int k = t + i * 256;
        float v = w[(size_t)e * C_DIM + k];
        __nv_bfloat16 h = __float2bfloat16(v);
        float r1 = v - __bfloat162float(h);
        __nv_bfloat16 m = __float2bfloat16(r1);
        float r2 = r1 - __bfloat162float(m);
        __nv_bfloat16 l = __float2bfloat16(r2);
        g_wsp[0][(size_t)e * C_DIM + k] = h;
        g_wsp[1][(size_t)e * C_DIM + k] = m;
        g_wsp[2][(size_t)e * C_DIM + k] = l;
    }
}

// ---------------- K1: HMMA bf16 GEMM (double-buffered) + fused epilogue ------
// One block per 128-token tile; 8 warps in 4(M)x2(N) grid: 32 tok x 32 exp each.
// Per buffer: A 3 levels x 128 rows x 128B = 48 KB, B 3 x 64 x 128B = 24 KB.
#define SM_BUF   73728               // 72 KB per buffer
#define SM_B_IN  49152               // B offset inside a buffer
#define SM_TOTAL (2 * SM_BUF)        // 144 KB

__global__ __launch_bounds__(256, 1)
void k_gemm_mma(const float* __restrict__ x) {
    extern __shared__ char smem[];
    const uint32_t sb = cvta_smem(smem);
    const int tid = threadIdx.x;
    const int wid = tid >> 5;
    const int lane = tid & 31;
    const int b = blockIdx.x;
    const int block_t0 = b * TMB;

    __shared__ int h0[N_EXP], h1[N_EXP];
    if (tid < N_EXP) { h0[tid] = 0; h1[tid] = 0; }

    const int wm = wid >> 1;        // 0..3  -> token rows wm*32
    const int wn = wid & 1;         // 0..1  -> expert cols wn*32
    const int R = wm * 32;
    const int Ecol = wn * 32;

    float acc[2][4][4];
#pragma unroll
    for (int mt = 0; mt < 2; mt++)
#pragma unroll
        for (int nt = 0; nt < 4; nt++)
#pragma unroll
            for (int q = 0; q < 4; q++) acc[mt][nt][q] = 0.0f;

    float4 xva[4], xvb[4];          // A prefetch registers

    auto gloadA = [&](int c) {
#pragma unroll
        for (int i = 0; i < 4; i++) {
            int u = tid + i * 256;
            int r = u >> 3, cu = u & 7;
            const float* src = x + (size_t)(block_t0 + r) * C_DIM + c * BKC + cu * 8;
            xva[i] = *(const float4*)src;
            xvb[i] = *(const float4*)(src + 4);
        }
    };

    auto sstoreA = [&](int buf) {
        char* base = smem + buf * SM_BUF;
#pragma unroll
        for (int i = 0; i < 4; i++) {
            int u = tid + i * 256;
            int r = u >> 3, cu = u & 7;
            float v[8] = {xva[i].x, xva[i].y, xva[i].z, xva[i].w,
                          xvb[i].x, xvb[i].y, xvb[i].z, xvb[i].w};
            uint32_t ph[4], pm[4], pl[4];
#pragma unroll
            for (int j = 0; j < 4; j++) {
                float vA = v[2 * j], vB = v[2 * j + 1];
                __nv_bfloat16 hA = __float2bfloat16(vA);
                float rA = vA - __bfloat162float(hA);
                __nv_bfloat16 mA = __float2bfloat16(rA);
                __nv_bfloat16 lA = __float2bfloat16(rA - __bfloat162float(mA));
                __nv_bfloat16 hB = __float2bfloat16(vB);
                float rB = vB - __bfloat162float(hB);
                __nv_bfloat16 mB = __float2bfloat16(rB);
                __nv_bfloat16 lB = __float2bfloat16(rB - __bfloat162float(mB));
                ph[j] = pack_bf2(hA, hB);
                pm[j] = pack_bf2(mA, mB);
                pl[j] = pack_bf2(lA, lB);
            }
            uint32_t dst = (uint32_t)(r * 128 + ((cu ^ (r & 7)) << 4));
            *(uint4*)(base + 0 * 16384 + dst) = make_uint4(ph[0], ph[1], ph[2], ph[3]);
            *(uint4*)(base + 1 * 16384 + dst) = make_uint4(pm[0], pm[1], pm[2], pm[3]);
            *(uint4*)(base + 2 * 16384 + dst) = make_uint4(pl[0], pl[1], pl[2], pl[3]);
        }
    };

    auto cpasyncB = [&](int c, int buf) {
        uint32_t bb = sb + buf * SM_BUF + SM_B_IN;
#pragma unroll
        for (int i = 0; i < 6; i++) {
            int u = tid + i * 256;          // 0..1535
            int l = u >> 9;                 // level 0..2
            int r = u & 511;
            int e = r >> 3, cu = r & 7;
            const void* src = &g_wsp[l][(size_t)e * C_DIM + c * BKC + cu * 8];
            uint32_t dst = bb + (uint32_t)(l * 8192 + e * 128 + ((cu ^ (e & 7)) << 4));
            asm volatile("cp.async.cg.shared.global [%0], [%1], 16;"
                         :: "r"(dst), "l"(src));
        }
        asm volatile("cp.async.commit_group;");
    };

    // ---- prologue: fill buffer 0 ----
    gloadA(0);
    cpasyncB(0, 0);
    sstoreA(0);
    asm volatile("cp.async.wait_group 0;");
    __syncthreads();

    for (int c = 0; c < NCHUNK; c++) {
        const int buf = c & 1;
        const uint32_t abase = sb + buf * SM_BUF;
        const uint32_t bbase = abase + SM_B_IN;

        if (c + 1 < NCHUNK) {
            gloadA(c + 1);              // LDG issued; consumed after MMAs
            cpasyncB(c + 1, buf ^ 1);   // async fill of other buffer
        }

        // ---- 6 split terms x 4 k16-steps ----
        const int ta[6] = {0, 0, 1, 0, 1, 2};
        const int tb[6] = {0, 1, 0, 2, 1, 0};
#pragma unroll
        for (int t = 0; t < 6; t++) {
            uint32_t ab = abase + ta[t] * 16384;
            uint32_t bb = bbase + tb[t] * 8192;
#pragma unroll
            for (int ks = 0; ks < 4; ks++) {
                uint32_t ra[2][4];
#pragma unroll
                for (int mt = 0; mt < 2; mt++) {
                    int row = R + mt * 16 + (lane & 15);
                    int unit = ks * 2 + (lane >> 4);
                    uint32_t addr = ab + row * 128 + ((unit ^ (row & 7)) << 4);
                    asm volatile(
                        "ldmatrix.sync.aligned.m8n8.x4.shared.b16 {%0,%1,%2,%3}, [%4];"
                        : "=r"(ra[mt][0]), "=r"(ra[mt][1]), "=r"(ra[mt][2]), "=r"(ra[mt][3])
                        : "r"(addr));
                }
                uint32_t rb[4][2];
#pragma unroll
                for (int ntp = 0; ntp < 2; ntp++) {
                    int grp = lane >> 3;
                    int nt_sel = grp >> 1;
                    int k_sel = grp & 1;
                    int n = Ecol + ntp * 16 + nt_sel * 8 + (lane & 7);
                    int unit = ks * 2 + k_sel;
                    uint32_t addr = bb + n * 128 + ((unit ^ (n & 7)) << 4);
                    uint32_t q0, q1, q2, q3;
                    asm volatile(
                        "ldmatrix.sync.aligned.m8n8.x4.shared.b16 {%0,%1,%2,%3}, [%4];"
                        : "=r"(q0), "=r"(q1), "=r"(q2), "=r"(q3)
                        : "r"(addr));
                    rb[ntp * 2 + 0][0] = q0; rb[ntp * 2 + 0][1] = q1;
                    rb[ntp * 2 + 1][0] = q2; rb[ntp * 2 + 1][1] = q3;
                }
#pragma unroll
                for (int mt = 0; mt < 2; mt++)
#pragma unroll
                    for (int nt = 0; nt < 4; nt++) {
                        asm volatile(
                            "mma.sync.aligned.m16n8k16.row.col.f32.bf16.bf16.f32 "
                            "{%0,%1,%2,%3}, {%4,%5,%6,%7}, {%8,%9}, {%0,%1,%2,%3};"
                            : "+f"(acc[mt][nt][0]), "+f"(acc[mt][nt][1]),
                              "+f"(acc[mt][nt][2]), "+f"(acc[mt][nt][3])
                            : "r"(ra[mt][0]), "r"(ra[mt][1]), "r"(ra[mt][2]), "r"(ra[mt][3]),
                              "r"(rb[nt][0]), "r"(rb[nt][1]));
                    }
            }
        }

        if (c + 1 < NCHUNK) sstoreA(buf ^ 1);   // convert under tensor shadow
        asm volatile("cp.async.wait_group 0;");
        __syncthreads();
    }

    // ---- epilogue: stage logits (reuse smem), top-2 + softmax + hist ----
    float* lg = (float*)smem;            // [128][65]
    const int LGS = 65;
#pragma unroll
    for (int mt = 0; mt < 2; mt++)
#pragma unroll
        for (int nt = 0; nt < 4; nt++) {
            int r0 = R + mt * 16 + (lane >> 2);
            int c0 = Ecol + nt * 8 + (lane & 3) * 2;
            lg[r0 * LGS + c0]           = acc[mt][nt][0];
            lg[r0 * LGS + c0 + 1]       = acc[mt][nt][1];
            lg[(r0 + 8) * LGS + c0]     = acc[mt][nt][2];
            lg[(r0 + 8) * LGS + c0 + 1] = acc[mt][nt][3];
        }
    __syncthreads();

    if (tid < TMB) {
        const float* row = &lg[tid * LGS];
        float b1 = -INFINITY, b2 = -INFINITY;
        int i1 = 0, i2 = 0;
#pragma unroll 8
        for (int e = 0; e < N_EXP; e++) {
            float v = row[e];
            if (v > b1) { b2 = b1; i2 = i1; b1 = v; i1 = e; }
            else if (v > b2) { b2 = v; i2 = e; }
        }
        float e2 = expf(b2 - b1);
        float inv = 1.0f / (1.0f + e2);
        int n = block_t0 + tid;
        g_top1[n] = i1; g_top2[n] = i2;
        g_p1[n] = inv;  g_p2[n] = e2 * inv;
        atomicAdd(&h0[i1], 1);
        atomicAdd(&h1[i2], 1);
    }
    __syncthreads();
    if (tid < N_EXP) {
        g_hist0[b * N_EXP + tid] = h0[tid];
        g_hist1[b * N_EXP + tid] = h1[tid];
    }
}

// ---------------- K2: parallel per-expert prefix over tiles ------------------
#define QPT (MAX_NB / 32)   // 4

__global__ void k_prefix(int NB) {
    const int e = blockIdx.x;
    const int lane = threadIdx.x;
    const int base = lane * QPT;

    int v[QPT];
#pragma unroll
    for (int q = 0; q < QPT; q++)
        v[q] = (base + q < NB) ? g_hist0[(base + q) * N_EXP + e] : 0;
    int s = 0;
#pragma unroll
    for (int q = 0; q < QPT; q++) s += v[q];
    int incl = s;
#pragma unroll
    for (int d = 1; d < 32; d <<= 1) {
        int t = __shfl_up_sync(0xffffffffu, incl, d);
        if (lane >= d) incl += t;
    }
    int run = incl - s;
#pragma unroll
    for (int q = 0; q < QPT; q++) {
        if (base + q < NB) g_off0[(base + q) * N_EXP + e] = run;
        run += v[q];
    }
    int total0 = __shfl_sync(0xffffffffu, incl, 31);

#pragma unroll
    for (int q = 0; q < QPT; q++)
        v[q] = (base + q < NB) ? g_hist1[(base + q) * N_EXP + e] : 0;
    s = 0;
#pragma unroll
    for (int q = 0; q < QPT; q++) s += v[q];
    incl = s;
#pragma unroll
    for (int d = 1; d < 32; d <<= 1) {
        int t = __shfl_up_sync(0xffffffffu, incl, d);
        if (lane >= d) incl += t;
    }
    run = total0 + (incl - s);
#pragma unroll
    for (int q = 0; q < QPT; q++) {
        if (base + q < NB) g_off1[(base + q) * N_EXP + e] = run;
        run += v[q];
    }
}

// ---------------- K3: ranks via match_any, capacity mask, all outputs --------
__global__ void k_final(int N, int cap, float* __restrict__ out, long out_elems) {
    __shared__ int s1[TMB], s2[TMB], r0[TMB], r1[TMB];
    __shared__ int wh0[4][N_EXP], wh1[4][N_EXP];

    const int tid = threadIdx.x;
    const int b = blockIdx.x;
    const int warp = tid >> 5;
    const int lane = tid & 31;
    const int n = b * TMB + tid;

#pragma unroll
    for (int i = 0; i < 2; i++) {
        (&wh0[0][0])[tid + i * 128] = 0;
        (&wh1[0][0])[tid + i * 128] = 0;
    }

    int e1  = g_top1[n];
    int e2v = g_top2[n];
    float p1v = g_p1[n];
    float p2v = g_p2[n];
    s1[tid] = e1; s2[tid] = e2v;
    __syncthreads();

    unsigned lt = (1u << lane) - 1u;
    unsigned m0 = __match_any_sync(0xffffffffu, e1);
    int rw0 = __popc(m0 & lt);
    if (rw0 == 0) wh0[warp][e1] = __popc(m0);
    unsigned m1 = __match_any_sync(0xffffffffu, e2v);
    int rw1 = __popc(m1 & lt);
    if (rw1 == 0) wh1[warp][e2v] = __popc(m1);
    __syncthreads();

    int add0 = 0, add1 = 0;
#pragma unroll
    for (int w = 0; w < 3; w++) {
        if (w < warp) { add0 += wh0[w][e1]; add1 += wh1[w][e2v]; }
    }
    int rr0 = g_off0[b * N_EXP + e1]  + rw0 + add0;
    int rr1 = g_off1[b * N_EXP + e2v] + rw1 + add1;
    r0[tid] = rr0; r1[tid] = rr1;

    // output layout (float32 elements):
    //   [0, N*128) mask | [N*128,+2N) probs | [+2N) idx | [+2N) rank | [1] cap
    const size_t off_probs = (size_t)N * 128;
    const size_t off_idx   = off_probs + (size_t)N * 2;
    const size_t off_rank  = off_idx + (size_t)N * 2;
    const size_t off_cap   = off_rank + (size_t)N * 2;

    size_t p;
    p = off_idx + (size_t)n * 2;
    if (p + 1 < (size_t)out_elems) { out[p] = (float)e1; out[p + 1] = (float)e2v; }
    p = off_rank + (size_t)n * 2;
    if (p + 1 < (size_t)out_elems) { out[p] = (float)rr0; out[p + 1] = (float)rr1; }
    p = off_probs + (size_t)n * 2;
    if (p + 1 < (size_t)out_elems) {
        out[p]     = (rr0 < cap) ? p1v : 0.0f;
        out[p + 1] = (rr1 < cap) ? p2v : 0.0f;
    }
    if (b == 0 && tid == 0 && off_cap < (size_t)out_elems) out[off_cap] = (float)cap;
    __syncthreads();

    // mask slab: lane writes float4 (4 expert cols) of one token row
    const int e_base = lane * 4;
    for (int i = warp; i < TMB; i += 4) {
        float4 v;
        if (lane < 16) {
            int s = s1[i]; bool ok = r0[i] < cap;
            v.x = (ok && s == e_base + 0) ? 1.0f : 0.0f;
            v.y = (ok && s == e_base + 1) ? 1.0f : 0.0f;
            v.z = (ok && s == e_base + 2) ? 1.0f : 0.0f;
            v.w = (ok && s == e_base + 3) ? 1.0f : 0.0f;
        } else {
            int s = s2[i] + 64; bool ok = r1[i] < cap;
            v.x = (ok && s == e_base + 0) ? 1.0f : 0.0f;
            v.y = (ok && s == e_base + 1) ? 1.0f : 0.0f;
            v.z = (ok && s == e_base + 2) ? 1.0f : 0.0f;
            v.w = (ok && s == e_base + 3) ? 1.0f : 0.0f;
        }
        size_t pos = (size_t)(b * TMB + i) * 128 + e_base;
        if (pos + 3 < (size_t)out_elems) *(float4*)&out[pos] = v;
    }
}

// ---------------- launch ------------------------------------------------------
extern "C" void kernel_launch(void* const* d_in, const int* in_sizes, int n_in,
                              void* d_out, int out_size) {
    const float* x = (const float*)d_in[0];
    const float* w = (const float*)d_in[1];
    int N = in_sizes[0] / C_DIM;              // 16384
    if (N > MAX_N) N = MAX_N;

    int cap = (int)((2.0 * 2.0 * (double)N) / 64.0);
    if (cap < 4) cap = 4;

    int NB = N / TMB;                         // 128

    cudaFuncSetAttribute(k_gemm_mma, cudaFuncAttributeMaxDynamicSharedMemorySize, SM_TOTAL);

    k_wsplit<<<N_EXP, 256>>>(w);
    k_gemm_mma<<<NB, 256, SM_TOTAL>>>(x);
    k_prefix<<<N_EXP, 32>>>(NB);
    k_final<<<NB, 128>>>(N, cap, (float*)d_out, (long)out_size);
}